// round 12
// baseline (speedup 1.0000x reference)
#include <cuda_runtime.h>
#include <cuda_fp16.h>
#include <cstdint>

// B=512, T=256, NE=384, H=64
__device__ __half g_qh [512*256*64];   // [b][t][h]  (pre-scaled by H^-0.5 * log2e)
__device__ __half g_kh [512*256*64];   // [b][t][h]
__device__ __half g_vTh[512*64*256];   // [b][h][t]

static __device__ __forceinline__ uint32_t pkh2(float lo, float hi){
  __half2 h = __floats2half2_rn(lo, hi);
  return *reinterpret_cast<uint32_t*>(&h);
}
static __device__ __forceinline__ uint32_t hex2(uint32_t v){
  uint32_t r; asm("ex2.approx.f16x2 %0, %1;" : "=r"(r) : "r"(v)); return r;
}
static __device__ __forceinline__ void mma16n8k16(float* d, const uint32_t* a, const uint32_t* b){
  asm volatile(
    "mma.sync.aligned.m16n8k16.row.col.f32.f16.f16.f32 "
    "{%0,%1,%2,%3}, {%4,%5,%6,%7}, {%8,%9}, {%0,%1,%2,%3};"
    : "+f"(d[0]), "+f"(d[1]), "+f"(d[2]), "+f"(d[3])
    : "r"(a[0]), "r"(a[1]), "r"(a[2]), "r"(a[3]), "r"(b[0]), "r"(b[1]));
}

// ---------------- QKV projection; W transposed+converted inline per k-tile ----------
// B-operand tile built from fp32 W each tile: coalesced LDG -> Wst [kk][n] stage ->
// transpose-convert to Bsh [n][kk] fp16 (pitch 40 halves, frag-load banks unchanged).
__global__ __launch_bounds__(256, 2) void qkv_mma(const float* __restrict__ x,
                                                  const float* __restrict__ Wk,
                                                  const float* __restrict__ Wq,
                                                  const float* __restrict__ Wv){
  __shared__ __half Ash[128*40];   // [m][k] pitch 40 halves
  __shared__ __half Bsh[192*40];   // [n][k] pitch 40 halves
  __shared__ float  Wst[32*196];   // [kk][n] fp32 stage, pitch 196
  const int tid = threadIdx.x, lane = tid & 31, warp = tid >> 5;
  const int g = lane >> 2, tig = lane & 3;
  const int wm = warp >> 2, wn = warp & 3;
  const int m0 = blockIdx.x * 128;
  const uint32_t* Aw = (const uint32_t*)Ash;
  const uint32_t* Bw = (const uint32_t*)Bsh;

  float C[4][6][4];
  #pragma unroll
  for (int mf = 0; mf < 4; mf++)
    #pragma unroll
    for (int nf = 0; nf < 6; nf++)
      { C[mf][nf][0]=0.f; C[mf][nf][1]=0.f; C[mf][nf][2]=0.f; C[mf][nf][3]=0.f; }

  // A prefetch: 128 rows x 8 float4-groups
  const int ar[4] = { tid>>3, (tid+256)>>3, (tid+512)>>3, (tid+768)>>3 };
  const int ac = tid & 7;

  float4 ra[4];
  #pragma unroll
  for (int it = 0; it < 4; it++)
    ra[it] = *(const float4*)(x + (size_t)(m0 + ar[it])*384 + ac*4);

  #pragma unroll 1
  for (int ti = 0; ti < 12; ti++){
    const int kt = ti * 32;
    // commit A
    #pragma unroll
    for (int it = 0; it < 4; it++){
      uint2 h2 = make_uint2(pkh2(ra[it].x, ra[it].y), pkh2(ra[it].z, ra[it].w));
      *(uint2*)(Ash + ar[it]*40 + ac*4) = h2;
    }
    // stage W fp32 tile: FULL 32 kk x 48 float4 = 1536 float4 in 6 rounds
    #pragma unroll
    for (int it = 0; it < 6; it++){
      const int i  = tid + 256*it;       // 0..1535
      const int wk = i / 48;             // 0..31
      const int wc = i % 48;             // 0..47 (float4 group over 192 n)
      const int mat = wc >> 4;           // 0=q, 1=k, 2=v
      const float* W = (mat == 0) ? Wq : (mat == 1 ? Wk : Wv);
      float4 v = *(const float4*)(W + (kt + wk)*64 + ((wc*4) & 63));
      *(float4*)(Wst + wk*196 + wc*4) = v;
    }
    __syncthreads();

    // B-fill: transpose-convert stage -> Bsh; lanes take consecutive n (conflict-free)
    #pragma unroll
    for (int it = 0; it < 6; it++){
      const int i = tid + 256*it;            // 0..1535
      const int Wt = i >> 5;                 // 0..47
      const int n  = (Wt % 6)*32 + (i & 31);
      const int k4 = Wt / 6;                 // 0..7
      float a0 = Wst[(k4*4+0)*196 + n];
      float a1 = Wst[(k4*4+1)*196 + n];
      float a2 = Wst[(k4*4+2)*196 + n];
      float a3 = Wst[(k4*4+3)*196 + n];
      uint2 h2 = make_uint2(pkh2(a0, a1), pkh2(a2, a3));
      *(uint2*)(Bsh + n*40 + k4*4) = h2;
    }
    if (ti < 11){   // prefetch next A tile (flies during barrier + MMAs)
      const int kn = kt + 32;
      #pragma unroll
      for (int it = 0; it < 4; it++)
        ra[it] = *(const float4*)(x + (size_t)(m0 + ar[it])*384 + kn + ac*4);
    }
    __syncthreads();

    #pragma unroll
    for (int ks = 0; ks < 2; ks++){
      const int ko = ks*8 + tig;
      uint32_t a[4][4];
      #pragma unroll
      for (int mf = 0; mf < 4; mf++){
        const int mr = wm*64 + mf*16;
        a[mf][0] = Aw[(mr+g  )*20 + ko    ];
        a[mf][1] = Aw[(mr+g+8)*20 + ko    ];
        a[mf][2] = Aw[(mr+g  )*20 + ko + 4];
        a[mf][3] = Aw[(mr+g+8)*20 + ko + 4];
      }
      #pragma unroll
      for (int nf = 0; nf < 6; nf++){
        const int nb = wn*48 + nf*8;
        uint32_t b[2] = { Bw[(nb+g)*20 + ko], Bw[(nb+g)*20 + ko + 4] };
        #pragma unroll
        for (int mf = 0; mf < 4; mf++)
          mma16n8k16(C[mf][nf], a[mf], b);
      }
    }
    __syncthreads();   // MMAs done before next commit overwrites Ash/Wst
  }

  // Epilogue: q scaled by 0.125*log2(e); k [t][h]; v [b][h][t]
  const float QS = 0.18033688f;
  const int bb = m0 >> 8;
  #pragma unroll
  for (int mf = 0; mf < 4; mf++){
    const int mlo = m0 + wm*64 + mf*16 + g;
    const int t = mlo & 255;
    #pragma unroll
    for (int nf = 0; nf < 6; nf++){
      const int n = wn*48 + nf*8 + 2*tig;
      const int id = n >> 6, h = n & 63;
      if (id == 2){         // v
        __half* base = g_vTh + (size_t)bb*16384;
        base[(h  )*256 + t    ] = __float2half(C[mf][nf][0]);
        base[(h+1)*256 + t    ] = __float2half(C[mf][nf][1]);
        base[(h  )*256 + t + 8] = __float2half(C[mf][nf][2]);
        base[(h+1)*256 + t + 8] = __float2half(C[mf][nf][3]);
      } else if (id == 1){  // k
        *(uint32_t*)(g_kh + (size_t)(mlo  )*64 + h) = pkh2(C[mf][nf][0], C[mf][nf][1]);
        *(uint32_t*)(g_kh + (size_t)(mlo+8)*64 + h) = pkh2(C[mf][nf][2], C[mf][nf][3]);
      } else {              // q
        *(uint32_t*)(g_qh + (size_t)(mlo  )*64 + h) = pkh2(C[mf][nf][0]*QS, C[mf][nf][1]*QS);
        *(uint32_t*)(g_qh + (size_t)(mlo+8)*64 + h) = pkh2(C[mf][nf][2]*QS, C[mf][nf][3]*QS);
      }
    }
  }
}

// ---------------- fp16 flash attention: 512 threads, one 16-row band per warp ------
// Warp w owns rows 16w..16w+15 (cd = w>>2 chunks). Short-band warps retire early,
// freeing issue/LSU slots for the long warps (latency-bound regime per R10).
// No-max exp2 softmax (bounded scores); P = ex2.approx.f16x2 == PV A-frag;
// l via 9th all-ones V tile (every accumulator column = row sum).
__global__ __launch_bounds__(512) void attn6(float* __restrict__ out){
  extern __shared__ __half smh[];
  __half* Ksh  = smh;            // [256][72]
  __half* Vtsh = smh + 256*72;   // [72][264]  rows 64..71: all ones
  const int b = blockIdx.x;
  const int tid = threadIdx.x, lane = tid & 31, w = tid >> 5;
  const int g = lane >> 2, tig = lane & 3;
  const uint32_t* Kw = (const uint32_t*)Ksh;
  const uint32_t* Vw = (const uint32_t*)Vtsh;

  {
    const uint4* Kg = (const uint4*)(g_kh  + (size_t)b*16384);
    const uint4* Vg = (const uint4*)(g_vTh + (size_t)b*16384);
    #pragma unroll
    for (int it = 0; it < 4; it++){
      int i = tid + 512*it;
      *(uint4*)(Ksh + (i>>3)*72 + (i&7)*8) = Kg[i];
      *(uint4*)(Vtsh + (i>>5)*264 + (i&31)*8) = Vg[i];
    }
    const __half one = __float2half(1.f);
    for (int i = tid; i < 2112; i += 512){
      int r = i/264, c1 = i - r*264;
      Vtsh[(64 + r)*264 + c1] = one;
    }
  }
  __syncthreads();

  const uint32_t* qp = (const uint32_t*)(g_qh + (size_t)b*16384);
  const int m0 = 16*w;

  uint32_t aq[4][4];
  #pragma unroll
  for (int ks = 0; ks < 4; ks++){
    const int ko = ks*8 + tig;
    aq[ks][0] = qp[(m0+g  )*32 + ko    ];
    aq[ks][1] = qp[(m0+g+8)*32 + ko    ];
    aq[ks][2] = qp[(m0+g  )*32 + ko + 4];
    aq[ks][3] = qp[(m0+g+8)*32 + ko + 4];
  }

  float O[9][4];
  #pragma unroll
  for (int jo = 0; jo < 9; jo++){ O[jo][0]=0.f; O[jo][1]=0.f; O[jo][2]=0.f; O[jo][3]=0.f; }
  const int cd = w >> 2;
  const int jmd = ((16*(w & 3) + 15) >> 3) + 1;   // 2,4,6,8 — live j-tiles on diagonal

  for (int c = 0; c <= cd; c++){
    const int jm = (c == cd) ? jmd : 8;
    float S[8][4];
    #pragma unroll
    for (int j = 0; j < 8; j++){ S[j][0]=0.f; S[j][1]=0.f; S[j][2]=0.f; S[j][3]=0.f; }

    #pragma unroll
    for (int ks = 0; ks < 4; ks++){
      const int ko = ks*8 + tig;
      #pragma unroll
      for (int j = 0; j < 8; j++){
        if (j < jm){
          const int kr = (c*64 + j*8 + g)*36 + ko;
          uint32_t bf[2] = { Kw[kr], Kw[kr + 4] };
          mma16n8k16(S[j], aq[ks], bf);
        }
      }
    }
    if (c == cd){   // causal mask: exp2(-100) == 0
      #pragma unroll
      for (int j = 0; j < 8; j++){
        if (j < jm){
          const int col = c*64 + j*8 + 2*tig;
          if (col     > m0+g  ) S[j][0] = -100.f;
          if (col + 1 > m0+g  ) S[j][1] = -100.f;
          if (col     > m0+g+8) S[j][2] = -100.f;
          if (col + 1 > m0+g+8) S[j][3] = -100.f;
        }
      }
    }

    // P = exp2(S) packed f16x2 == PV A-frags; 9th jo tile accumulates row sums
    #pragma unroll
    for (int kk = 0; kk < 4; kk++){
      if (2*kk < jm){
        uint32_t ap[4];
        ap[0] = hex2(pkh2(S[2*kk  ][0], S[2*kk  ][1]));
        ap[1] = hex2(pkh2(S[2*kk  ][2], S[2*kk  ][3]));
        ap[2] = hex2(pkh2(S[2*kk+1][0], S[2*kk+1][1]));
        ap[3] = hex2(pkh2(S[2*kk+1][2], S[2*kk+1][3]));
        const int tb = c*32 + kk*8 + tig;
        #pragma unroll
        for (int jo = 0; jo < 9; jo++){
          const int vr = (jo*8 + g)*132 + tb;
          uint32_t bv[2] = { Vw[vr], Vw[vr + 4] };
          mma16n8k16(O[jo], ap, bv);
        }
      }
    }
  }

  const float inv0 = 1.0f / O[8][0], inv1 = 1.0f / O[8][2];
  float* ob = out + (size_t)b*16384;
  #pragma unroll
  for (int jo = 0; jo < 8; jo++){
    *(float2*)(ob + (m0+g  )*64 + jo*8 + 2*tig) = make_float2(O[jo][0]*inv0, O[jo][1]*inv0);
    *(float2*)(ob + (m0+g+8)*64 + jo*8 + 2*tig) = make_float2(O[jo][2]*inv1, O[jo][3]*inv1);
  }
}

extern "C" void kernel_launch(void* const* d_in, const int* in_sizes, int n_in,
                              void* d_out, int out_size) {
  const float* x  = (const float*)d_in[0];
  const float* Wk = (const float*)d_in[1];
  const float* Wq = (const float*)d_in[2];
  const float* Wv = (const float*)d_in[3];
  float* out = (float*)d_out;
  (void)in_sizes; (void)n_in; (void)out_size;

  cudaFuncSetAttribute(attn6, cudaFuncAttributeMaxDynamicSharedMemorySize, 74880);

  qkv_mma<<<1024, 256>>>(x, Wk, Wq, Wv);
  attn6<<<512, 512, 74880>>>(out);
}

// round 13
// speedup vs baseline: 1.8390x; 1.8390x over previous
#include <cuda_runtime.h>
#include <cuda_fp16.h>
#include <cstdint>

// B=512, T=256, NE=384, H=64
__device__ __half g_qh [512*256*64];   // [b][t][h]  (pre-scaled by H^-0.5 * log2e)
__device__ __half g_kh [512*256*64];   // [b][t][h]
__device__ __half g_vTh[512*64*256];   // [b][h][t]
__device__ __half g_WTh[192*384];      // [n][k]  n: 0-63 Wq, 64-127 Wk, 128-191 Wv

static __device__ __forceinline__ uint32_t pkh2(float lo, float hi){
  __half2 h = __floats2half2_rn(lo, hi);
  return *reinterpret_cast<uint32_t*>(&h);
}
static __device__ __forceinline__ uint32_t hex2(uint32_t v){
  uint32_t r; asm("ex2.approx.f16x2 %0, %1;" : "=r"(r) : "r"(v)); return r;
}
static __device__ __forceinline__ uint32_t smem_u32(const void* p){
  uint32_t a;
  asm("{ .reg .u64 t; cvta.to.shared.u64 t, %1; cvt.u32.u64 %0, t; }" : "=r"(a) : "l"(p));
  return a;
}
static __device__ __forceinline__ void cpasync16(uint32_t dst, const void* src){
  asm volatile("cp.async.cg.shared.global [%0], [%1], 16;" :: "r"(dst), "l"(src));
}
static __device__ __forceinline__ void mma16n8k16(float* d, const uint32_t* a, const uint32_t* b){
  asm volatile(
    "mma.sync.aligned.m16n8k16.row.col.f32.f16.f16.f32 "
    "{%0,%1,%2,%3}, {%4,%5,%6,%7}, {%8,%9}, {%0,%1,%2,%3};"
    : "+f"(d[0]), "+f"(d[1]), "+f"(d[2]), "+f"(d[3])
    : "r"(a[0]), "r"(a[1]), "r"(a[2]), "r"(a[3]), "r"(b[0]), "r"(b[1]));
}

// ---------------- W transpose + fp16 convert (R8-verified simple form) ----------------
__global__ void wt_kernel(const float* __restrict__ Wk, const float* __restrict__ Wq,
                          const float* __restrict__ Wv){
  const int n = blockIdx.x;
  const int c = n & 63;
  const float* W = (n < 64) ? Wq : (n < 128 ? Wk : Wv);
  for (int k = threadIdx.x; k < 384; k += 128)
    g_WTh[n*384 + k] = __float2half(W[k*64 + c]);
}

// ---------------- QKV projection: double-buffered, cp.async B, 1 sync/tile ----------
__global__ __launch_bounds__(256, 2) void qkv_mma(const float* __restrict__ x){
  __shared__ __half Ash[2][128*40];   // [m][k] pitch 40 halves
  __shared__ __half Bsh[2][192*40];   // [n][k] pitch 40 halves
  const int tid = threadIdx.x, lane = tid & 31, warp = tid >> 5;
  const int g = lane >> 2, tig = lane & 3;
  const int wm = warp >> 2, wn = warp & 3;
  const int m0 = blockIdx.x * 128;

  float C[4][6][4];
  #pragma unroll
  for (int mf = 0; mf < 4; mf++)
    #pragma unroll
    for (int nf = 0; nf < 6; nf++)
      { C[mf][nf][0]=0.f; C[mf][nf][1]=0.f; C[mf][nf][2]=0.f; C[mf][nf][3]=0.f; }

  // A prefetch: 128 rows x 8 float4-groups (verified mapping)
  const int ar[4] = { tid>>3, (tid+256)>>3, (tid+512)>>3, (tid+768)>>3 };
  const int ac = tid & 7;
  // B cp.async mapping: 768 16B-chunks/tile, 3 per thread
  const int bn[3] = { tid>>2, (tid+256)>>2, (tid+512)>>2 };   // n row 0..191
  const int bc = tid & 3;                                      // chunk (8 halves)

  float4 ra[4];
  #pragma unroll
  for (int it = 0; it < 4; it++)
    ra[it] = *(const float4*)(x + (size_t)(m0 + ar[it])*384 + ac*4);
  // B tile 0 -> buffer 0
  #pragma unroll
  for (int it = 0; it < 3; it++)
    cpasync16(smem_u32(&Bsh[0][bn[it]*40 + bc*8]), g_WTh + bn[it]*384 + bc*8);
  asm volatile("cp.async.commit_group;");

  #pragma unroll 1
  for (int ti = 0; ti < 12; ti++){
    const int cur = ti & 1;
    const uint32_t* Aw = (const uint32_t*)Ash[cur];
    const uint32_t* Bw = (const uint32_t*)Bsh[cur];

    // commit A(ti) into Ash[cur]  (prev reader MMA(ti-2) retired before sync(ti-1))
    #pragma unroll
    for (int it = 0; it < 4; it++){
      uint2 h2 = make_uint2(pkh2(ra[it].x, ra[it].y), pkh2(ra[it].z, ra[it].w));
      *(uint2*)(&Ash[cur][ar[it]*40 + ac*4]) = h2;
    }
    if (ti < 11){   // LDG A(ti+1): flies under everything below
      const int kn = (ti + 1) * 32;
      #pragma unroll
      for (int it = 0; it < 4; it++)
        ra[it] = *(const float4*)(x + (size_t)(m0 + ar[it])*384 + kn + ac*4);
    }
    asm volatile("cp.async.wait_group 0;");   // B(ti) landed (this thread)
    __syncthreads();                          // all A/B(ti) visible; MMA(ti-1) done
    if (ti < 11){   // B(ti+1) -> other buffer; overlaps MMA(ti)
      const int kn = (ti + 1) * 32;
      #pragma unroll
      for (int it = 0; it < 3; it++)
        cpasync16(smem_u32(&Bsh[cur^1][bn[it]*40 + bc*8]), g_WTh + bn[it]*384 + kn + bc*8);
      asm volatile("cp.async.commit_group;");
    }

    #pragma unroll
    for (int ks = 0; ks < 2; ks++){
      const int ko = ks*8 + tig;
      uint32_t a[4][4];
      #pragma unroll
      for (int mf = 0; mf < 4; mf++){
        const int mr = wm*64 + mf*16;
        a[mf][0] = Aw[(mr+g  )*20 + ko    ];
        a[mf][1] = Aw[(mr+g+8)*20 + ko    ];
        a[mf][2] = Aw[(mr+g  )*20 + ko + 4];
        a[mf][3] = Aw[(mr+g+8)*20 + ko + 4];
      }
      #pragma unroll
      for (int nf = 0; nf < 6; nf++){
        const int nb = wn*48 + nf*8;
        uint32_t b[2] = { Bw[(nb+g)*20 + ko], Bw[(nb+g)*20 + ko + 4] };
        #pragma unroll
        for (int mf = 0; mf < 4; mf++)
          mma16n8k16(C[mf][nf], a[mf], b);
      }
    }
  }

  // Epilogue: q scaled by 0.125*log2(e); k [t][h]; v [b][h][t]
  const float QS = 0.18033688f;
  const int bb = m0 >> 8;
  #pragma unroll
  for (int mf = 0; mf < 4; mf++){
    const int mlo = m0 + wm*64 + mf*16 + g;
    const int t = mlo & 255;
    #pragma unroll
    for (int nf = 0; nf < 6; nf++){
      const int n = wn*48 + nf*8 + 2*tig;
      const int id = n >> 6, h = n & 63;
      if (id == 2){         // v
        __half* base = g_vTh + (size_t)bb*16384;
        base[(h  )*256 + t    ] = __float2half(C[mf][nf][0]);
        base[(h+1)*256 + t    ] = __float2half(C[mf][nf][1]);
        base[(h  )*256 + t + 8] = __float2half(C[mf][nf][2]);
        base[(h+1)*256 + t + 8] = __float2half(C[mf][nf][3]);
      } else if (id == 1){  // k
        *(uint32_t*)(g_kh + (size_t)(mlo  )*64 + h) = pkh2(C[mf][nf][0], C[mf][nf][1]);
        *(uint32_t*)(g_kh + (size_t)(mlo+8)*64 + h) = pkh2(C[mf][nf][2], C[mf][nf][3]);
      } else {              // q
        *(uint32_t*)(g_qh + (size_t)(mlo  )*64 + h) = pkh2(C[mf][nf][0]*QS, C[mf][nf][1]*QS);
        *(uint32_t*)(g_qh + (size_t)(mlo+8)*64 + h) = pkh2(C[mf][nf][2]*QS, C[mf][nf][3]*QS);
      }
    }
  }
}

// ---------------- fp16 flash attention (R12-verified, 35.6us) ----------------
__global__ __launch_bounds__(512) void attn6(float* __restrict__ out){
  extern __shared__ __half smh[];
  __half* Ksh  = smh;            // [256][72]
  __half* Vtsh = smh + 256*72;   // [72][264]  rows 64..71: all ones
  const int b = blockIdx.x;
  const int tid = threadIdx.x, lane = tid & 31, w = tid >> 5;
  const int g = lane >> 2, tig = lane & 3;
  const uint32_t* Kw = (const uint32_t*)Ksh;
  const uint32_t* Vw = (const uint32_t*)Vtsh;

  {
    const uint4* Kg = (const uint4*)(g_kh  + (size_t)b*16384);
    const uint4* Vg = (const uint4*)(g_vTh + (size_t)b*16384);
    #pragma unroll
    for (int it = 0; it < 4; it++){
      int i = tid + 512*it;
      *(uint4*)(Ksh + (i>>3)*72 + (i&7)*8) = Kg[i];
      *(uint4*)(Vtsh + (i>>5)*264 + (i&31)*8) = Vg[i];
    }
    const __half one = __float2half(1.f);
    for (int i = tid; i < 2112; i += 512){
      int r = i/264, c1 = i - r*264;
      Vtsh[(64 + r)*264 + c1] = one;
    }
  }
  __syncthreads();

  const uint32_t* qp = (const uint32_t*)(g_qh + (size_t)b*16384);
  const int m0 = 16*w;

  uint32_t aq[4][4];
  #pragma unroll
  for (int ks = 0; ks < 4; ks++){
    const int ko = ks*8 + tig;
    aq[ks][0] = qp[(m0+g  )*32 + ko    ];
    aq[ks][1] = qp[(m0+g+8)*32 + ko    ];
    aq[ks][2] = qp[(m0+g  )*32 + ko + 4];
    aq[ks][3] = qp[(m0+g+8)*32 + ko + 4];
  }

  float O[9][4];
  #pragma unroll
  for (int jo = 0; jo < 9; jo++){ O[jo][0]=0.f; O[jo][1]=0.f; O[jo][2]=0.f; O[jo][3]=0.f; }
  const int cd = w >> 2;
  const int jmd = ((16*(w & 3) + 15) >> 3) + 1;   // 2,4,6,8 — live j-tiles on diagonal

  for (int c = 0; c <= cd; c++){
    const int jm = (c == cd) ? jmd : 8;
    float S[8][4];
    #pragma unroll
    for (int j = 0; j < 8; j++){ S[j][0]=0.f; S[j][1]=0.f; S[j][2]=0.f; S[j][3]=0.f; }

    #pragma unroll
    for (int ks = 0; ks < 4; ks++){
      const int ko = ks*8 + tig;
      #pragma unroll
      for (int j = 0; j < 8; j++){
        if (j < jm){
          const int kr = (c*64 + j*8 + g)*36 + ko;
          uint32_t bf[2] = { Kw[kr], Kw[kr + 4] };
          mma16n8k16(S[j], aq[ks], bf);
        }
      }
    }
    if (c == cd){   // causal mask: exp2(-100) == 0
      #pragma unroll
      for (int j = 0; j < 8; j++){
        if (j < jm){
          const int col = c*64 + j*8 + 2*tig;
          if (col     > m0+g  ) S[j][0] = -100.f;
          if (col + 1 > m0+g  ) S[j][1] = -100.f;
          if (col     > m0+g+8) S[j][2] = -100.f;
          if (col + 1 > m0+g+8) S[j][3] = -100.f;
        }
      }
    }

    #pragma unroll
    for (int kk = 0; kk < 4; kk++){
      if (2*kk < jm){
        uint32_t ap[4];
        ap[0] = hex2(pkh2(S[2*kk  ][0], S[2*kk  ][1]));
        ap[1] = hex2(pkh2(S[2*kk  ][2], S[2*kk  ][3]));
        ap[2] = hex2(pkh2(S[2*kk+1][0], S[2*kk+1][1]));
        ap[3] = hex2(pkh2(S[2*kk+1][2], S[2*kk+1][3]));
        const int tb = c*32 + kk*8 + tig;
        #pragma unroll
        for (int jo = 0; jo < 9; jo++){
          const int vr = (jo*8 + g)*132 + tb;
          uint32_t bv[2] = { Vw[vr], Vw[vr + 4] };
          mma16n8k16(O[jo], ap, bv);
        }
      }
    }
  }

  const float inv0 = 1.0f / O[8][0], inv1 = 1.0f / O[8][2];
  float* ob = out + (size_t)b*16384;
  #pragma unroll
  for (int jo = 0; jo < 8; jo++){
    *(float2*)(ob + (m0+g  )*64 + jo*8 + 2*tig) = make_float2(O[jo][0]*inv0, O[jo][1]*inv0);
    *(float2*)(ob + (m0+g+8)*64 + jo*8 + 2*tig) = make_float2(O[jo][2]*inv1, O[jo][3]*inv1);
  }
}

extern "C" void kernel_launch(void* const* d_in, const int* in_sizes, int n_in,
                              void* d_out, int out_size) {
  const float* x  = (const float*)d_in[0];
  const float* Wk = (const float*)d_in[1];
  const float* Wq = (const float*)d_in[2];
  const float* Wv = (const float*)d_in[3];
  float* out = (float*)d_out;
  (void)in_sizes; (void)n_in; (void)out_size;

  cudaFuncSetAttribute(attn6, cudaFuncAttributeMaxDynamicSharedMemorySize, 74880);

  wt_kernel<<<192, 128>>>(Wk, Wq, Wv);
  qkv_mma<<<1024, 256>>>(x);
  attn6<<<512, 512, 74880>>>(out);
}

// round 14
// speedup vs baseline: 1.9466x; 1.0585x over previous
#include <cuda_runtime.h>
#include <cuda_fp16.h>
#include <cstdint>

// B=512, T=256, NE=384, H=64
__device__ __half g_qh [512*256*64];   // [b][t][h]  (pre-scaled by H^-0.5 * log2e)
__device__ __half g_kh [512*256*64];   // [b][t][h]
__device__ __half g_vTh[512*64*256];   // [b][h][t]
__device__ __half g_WTh[192*384];      // [n][k]  n: 0-63 Wq, 64-127 Wk, 128-191 Wv

static __device__ __forceinline__ uint32_t pkh2(float lo, float hi){
  __half2 h = __floats2half2_rn(lo, hi);
  return *reinterpret_cast<uint32_t*>(&h);
}
static __device__ __forceinline__ uint32_t hex2(uint32_t v){
  uint32_t r; asm("ex2.approx.f16x2 %0, %1;" : "=r"(r) : "r"(v)); return r;
}
static __device__ __forceinline__ uint32_t smem_u32(const void* p){
  uint32_t a;
  asm("{ .reg .u64 t; cvta.to.shared.u64 t, %1; cvt.u32.u64 %0, t; }" : "=r"(a) : "l"(p));
  return a;
}
static __device__ __forceinline__ void ldm_x4(uint32_t* r, uint32_t addr){
  asm volatile("ldmatrix.sync.aligned.m8n8.x4.shared.b16 {%0,%1,%2,%3}, [%4];"
    : "=r"(r[0]), "=r"(r[1]), "=r"(r[2]), "=r"(r[3]) : "r"(addr));
}
static __device__ __forceinline__ void mma16n8k16(float* d, const uint32_t* a, const uint32_t* b){
  asm volatile(
    "mma.sync.aligned.m16n8k16.row.col.f32.f16.f16.f32 "
    "{%0,%1,%2,%3}, {%4,%5,%6,%7}, {%8,%9}, {%0,%1,%2,%3};"
    : "+f"(d[0]), "+f"(d[1]), "+f"(d[2]), "+f"(d[3])
    : "r"(a[0]), "r"(a[1]), "r"(a[2]), "r"(a[3]), "r"(b[0]), "r"(b[1]));
}

// ---------------- W transpose + fp16 convert (R8-verified, 5.9us) ----------------
__global__ void wt_kernel(const float* __restrict__ Wk, const float* __restrict__ Wq,
                          const float* __restrict__ Wv){
  const int n = blockIdx.x;
  const int c = n & 63;
  const float* W = (n < 64) ? Wq : (n < 128 ? Wk : Wv);
  for (int k = threadIdx.x; k < 384; k += 128)
    g_WTh[n*384 + k] = __float2half(W[k*64 + c]);
}

// ---------------- QKV projection: R10 structure + ldmatrix fragment loads ----------
// 8 warps = 2(M) x 4(N); warp tile 64x48; k-tiles of 32 (2 k16 steps).
// Frag loads: 8 ldmatrix.x4 (A) + 6 (B) per tile/warp, replacing 56 scalar LDS.32.
// Pitch 40 halves = 80B rows: 8-row ldmatrix address set tiles 0..127 mod 128 -> conflict-free.
__global__ __launch_bounds__(256) void qkv_mma(const float* __restrict__ x){
  __shared__ __half Ash[128*40];   // [m][k] pitch 40 halves
  __shared__ __half Bsh[192*40];   // [n][k] pitch 40 halves
  const int tid = threadIdx.x, lane = tid & 31, warp = tid >> 5;
  const int g = lane >> 2, tig = lane & 3;
  const int wm = warp >> 2, wn = warp & 3;
  const int m0 = blockIdx.x * 128;

  float C[4][6][4];
  #pragma unroll
  for (int mf = 0; mf < 4; mf++)
    #pragma unroll
    for (int nf = 0; nf < 6; nf++)
      { C[mf][nf][0]=0.f; C[mf][nf][1]=0.f; C[mf][nf][2]=0.f; C[mf][nf][3]=0.f; }

  // ldmatrix per-lane address bases
  const int a_ro = lane & 15;                         // row offset within 16-row tile
  const int a_co = (lane & 16) >> 1;                  // +8 halves for k-hi matrices
  const int b_ro = (lane & 7) | ((lane & 16) >> 1);   // row offset within 16-n tile
  const int b_co = lane & 8;                          // +8 halves for k-hi matrices
  const uint32_t a_base = smem_u32(Ash) + 2*((wm*64 + a_ro)*40 + a_co);
  const uint32_t b_base = smem_u32(Bsh) + 2*((wn*48 + b_ro)*40 + b_co);

  // prefetch indices: A 128 rows x 8 float4-groups; B 192n x 4 uint4-groups
  const int ar[4] = { tid>>3, (tid+256)>>3, (tid+512)>>3, (tid+768)>>3 };
  const int ac = tid & 7;
  const int br[3] = { tid>>2, (tid+256)>>2, (tid+512)>>2 };
  const int bg = tid & 3;
  const uint4* Wg = (const uint4*)g_WTh;

  float4 ra[4]; uint4 rb[3];
  #pragma unroll
  for (int it = 0; it < 4; it++)
    ra[it] = *(const float4*)(x + (size_t)(m0 + ar[it])*384 + ac*4);
  #pragma unroll
  for (int it = 0; it < 3; it++)
    rb[it] = Wg[br[it]*48 + bg];

  #pragma unroll 1
  for (int ti = 0; ti < 12; ti++){
    // commit prefetched tile
    #pragma unroll
    for (int it = 0; it < 4; it++){
      uint2 h2 = make_uint2(pkh2(ra[it].x, ra[it].y), pkh2(ra[it].z, ra[it].w));
      *(uint2*)(Ash + ar[it]*40 + ac*4) = h2;
    }
    #pragma unroll
    for (int it = 0; it < 3; it++)
      *(uint4*)(Bsh + br[it]*40 + bg*8) = rb[it];
    __syncthreads();

    if (ti < 11){   // prefetch next k-tile (flies during the MMAs)
      const int kn = (ti + 1) * 32;
      #pragma unroll
      for (int it = 0; it < 4; it++)
        ra[it] = *(const float4*)(x + (size_t)(m0 + ar[it])*384 + kn + ac*4);
      #pragma unroll
      for (int it = 0; it < 3; it++)
        rb[it] = Wg[br[it]*48 + kn/8 + bg];
    }

    #pragma unroll
    for (int ks = 0; ks < 2; ks++){
      uint32_t a[4][4];
      #pragma unroll
      for (int mf = 0; mf < 4; mf++)
        ldm_x4(a[mf], a_base + mf*1280 + ks*32);
      uint32_t bf[6][2];
      #pragma unroll
      for (int p = 0; p < 3; p++){
        uint32_t t[4];
        ldm_x4(t, b_base + p*1280 + ks*32);
        bf[2*p  ][0] = t[0]; bf[2*p  ][1] = t[1];
        bf[2*p+1][0] = t[2]; bf[2*p+1][1] = t[3];
      }
      #pragma unroll
      for (int nf = 0; nf < 6; nf++)
        #pragma unroll
        for (int mf = 0; mf < 4; mf++)
          mma16n8k16(C[mf][nf], a[mf], bf[nf]);
    }
    __syncthreads();
  }

  // Epilogue: q scaled by 0.125*log2(e); k [t][h]; v [b][h][t]
  const float QS = 0.18033688f;
  const int bb = m0 >> 8;
  #pragma unroll
  for (int mf = 0; mf < 4; mf++){
    const int mlo = m0 + wm*64 + mf*16 + g;
    const int t = mlo & 255;
    #pragma unroll
    for (int nf = 0; nf < 6; nf++){
      const int n = wn*48 + nf*8 + 2*tig;
      const int id = n >> 6, h = n & 63;
      if (id == 2){         // v
        __half* base = g_vTh + (size_t)bb*16384;
        base[(h  )*256 + t    ] = __float2half(C[mf][nf][0]);
        base[(h+1)*256 + t    ] = __float2half(C[mf][nf][1]);
        base[(h  )*256 + t + 8] = __float2half(C[mf][nf][2]);
        base[(h+1)*256 + t + 8] = __float2half(C[mf][nf][3]);
      } else if (id == 1){  // k
        *(uint32_t*)(g_kh + (size_t)(mlo  )*64 + h) = pkh2(C[mf][nf][0], C[mf][nf][1]);
        *(uint32_t*)(g_kh + (size_t)(mlo+8)*64 + h) = pkh2(C[mf][nf][2], C[mf][nf][3]);
      } else {              // q
        *(uint32_t*)(g_qh + (size_t)(mlo  )*64 + h) = pkh2(C[mf][nf][0]*QS, C[mf][nf][1]*QS);
        *(uint32_t*)(g_qh + (size_t)(mlo+8)*64 + h) = pkh2(C[mf][nf][2]*QS, C[mf][nf][3]*QS);
      }
    }
  }
}

// ---------------- fp16 flash attention (R12/R13-verified, 35.6us) ----------------
__global__ __launch_bounds__(512) void attn6(float* __restrict__ out){
  extern __shared__ __half smh[];
  __half* Ksh  = smh;            // [256][72]
  __half* Vtsh = smh + 256*72;   // [72][264]  rows 64..71: all ones
  const int b = blockIdx.x;
  const int tid = threadIdx.x, lane = tid & 31, w = tid >> 5;
  const int g = lane >> 2, tig = lane & 3;
  const uint32_t* Kw = (const uint32_t*)Ksh;
  const uint32_t* Vw = (const uint32_t*)Vtsh;

  {
    const uint4* Kg = (const uint4*)(g_kh  + (size_t)b*16384);
    const uint4* Vg = (const uint4*)(g_vTh + (size_t)b*16384);
    #pragma unroll
    for (int it = 0; it < 4; it++){
      int i = tid + 512*it;
      *(uint4*)(Ksh + (i>>3)*72 + (i&7)*8) = Kg[i];
      *(uint4*)(Vtsh + (i>>5)*264 + (i&31)*8) = Vg[i];
    }
    const __half one = __float2half(1.f);
    for (int i = tid; i < 2112; i += 512){
      int r = i/264, c1 = i - r*264;
      Vtsh[(64 + r)*264 + c1] = one;
    }
  }
  __syncthreads();

  const uint32_t* qp = (const uint32_t*)(g_qh + (size_t)b*16384);
  const int m0 = 16*w;

  uint32_t aq[4][4];
  #pragma unroll
  for (int ks = 0; ks < 4; ks++){
    const int ko = ks*8 + tig;
    aq[ks][0] = qp[(m0+g  )*32 + ko    ];
    aq[ks][1] = qp[(m0+g+8)*32 + ko    ];
    aq[ks][2] = qp[(m0+g  )*32 + ko + 4];
    aq[ks][3] = qp[(m0+g+8)*32 + ko + 4];
  }

  float O[9][4];
  #pragma unroll
  for (int jo = 0; jo < 9; jo++){ O[jo][0]=0.f; O[jo][1]=0.f; O[jo][2]=0.f; O[jo][3]=0.f; }
  const int cd = w >> 2;
  const int jmd = ((16*(w & 3) + 15) >> 3) + 1;   // 2,4,6,8 — live j-tiles on diagonal

  for (int c = 0; c <= cd; c++){
    const int jm = (c == cd) ? jmd : 8;
    float S[8][4];
    #pragma unroll
    for (int j = 0; j < 8; j++){ S[j][0]=0.f; S[j][1]=0.f; S[j][2]=0.f; S[j][3]=0.f; }

    #pragma unroll
    for (int ks = 0; ks < 4; ks++){
      const int ko = ks*8 + tig;
      #pragma unroll
      for (int j = 0; j < 8; j++){
        if (j < jm){
          const int kr = (c*64 + j*8 + g)*36 + ko;
          uint32_t bf[2] = { Kw[kr], Kw[kr + 4] };
          mma16n8k16(S[j], aq[ks], bf);
        }
      }
    }
    if (c == cd){   // causal mask: exp2(-100) == 0
      #pragma unroll
      for (int j = 0; j < 8; j++){
        if (j < jm){
          const int col = c*64 + j*8 + 2*tig;
          if (col     > m0+g  ) S[j][0] = -100.f;
          if (col + 1 > m0+g  ) S[j][1] = -100.f;
          if (col     > m0+g+8) S[j][2] = -100.f;
          if (col + 1 > m0+g+8) S[j][3] = -100.f;
        }
      }
    }

    #pragma unroll
    for (int kk = 0; kk < 4; kk++){
      if (2*kk < jm){
        uint32_t ap[4];
        ap[0] = hex2(pkh2(S[2*kk  ][0], S[2*kk  ][1]));
        ap[1] = hex2(pkh2(S[2*kk  ][2], S[2*kk  ][3]));
        ap[2] = hex2(pkh2(S[2*kk+1][0], S[2*kk+1][1]));
        ap[3] = hex2(pkh2(S[2*kk+1][2], S[2*kk+1][3]));
        const int tb = c*32 + kk*8 + tig;
        #pragma unroll
        for (int jo = 0; jo < 9; jo++){
          const int vr = (jo*8 + g)*132 + tb;
          uint32_t bv[2] = { Vw[vr], Vw[vr + 4] };
          mma16n8k16(O[jo], ap, bv);
        }
      }
    }
  }

  const float inv0 = 1.0f / O[8][0], inv1 = 1.0f / O[8][2];
  float* ob = out + (size_t)b*16384;
  #pragma unroll
  for (int jo = 0; jo < 8; jo++){
    *(float2*)(ob + (m0+g  )*64 + jo*8 + 2*tig) = make_float2(O[jo][0]*inv0, O[jo][1]*inv0);
    *(float2*)(ob + (m0+g+8)*64 + jo*8 + 2*tig) = make_float2(O[jo][2]*inv1, O[jo][3]*inv1);
  }
}

extern "C" void kernel_launch(void* const* d_in, const int* in_sizes, int n_in,
                              void* d_out, int out_size) {
  const float* x  = (const float*)d_in[0];
  const float* Wk = (const float*)d_in[1];
  const float* Wq = (const float*)d_in[2];
  const float* Wv = (const float*)d_in[3];
  float* out = (float*)d_out;
  (void)in_sizes; (void)n_in; (void)out_size;

  cudaFuncSetAttribute(attn6, cudaFuncAttributeMaxDynamicSharedMemorySize, 74880);

  wt_kernel<<<192, 128>>>(Wk, Wq, Wv);
  qkv_mma<<<1024, 256>>>(x);
  attn6<<<512, 512, 74880>>>(out);
}

// round 15
// speedup vs baseline: 2.0277x; 1.0417x over previous
#include <cuda_runtime.h>
#include <cuda_fp16.h>
#include <cstdint>

// B=512, T=256, NE=384, H=64
__device__ __half g_qh [512*256*64];   // [b][t][h]  (pre-scaled by H^-0.5 * log2e)
__device__ __half g_kh [512*256*64];   // [b][t][h]
__device__ __half g_vTh[512*64*256];   // [b][h][t]
__device__ __half g_WTh[192*384];      // [n][k]  n: 0-63 Wq, 64-127 Wk, 128-191 Wv

static __device__ __forceinline__ uint32_t pkh2(float lo, float hi){
  __half2 h = __floats2half2_rn(lo, hi);
  return *reinterpret_cast<uint32_t*>(&h);
}
static __device__ __forceinline__ uint32_t hex2(uint32_t v){
  uint32_t r; asm("ex2.approx.f16x2 %0, %1;" : "=r"(r) : "r"(v)); return r;
}
static __device__ __forceinline__ uint32_t smem_u32(const void* p){
  uint32_t a;
  asm("{ .reg .u64 t; cvta.to.shared.u64 t, %1; cvt.u32.u64 %0, t; }" : "=r"(a) : "l"(p));
  return a;
}
static __device__ __forceinline__ void ldm_x4(uint32_t* r, uint32_t addr){
  asm volatile("ldmatrix.sync.aligned.m8n8.x4.shared.b16 {%0,%1,%2,%3}, [%4];"
    : "=r"(r[0]), "=r"(r[1]), "=r"(r[2]), "=r"(r[3]) : "r"(addr));
}
static __device__ __forceinline__ void mma16n8k16(float* d, const uint32_t* a, const uint32_t* b){
  asm volatile(
    "mma.sync.aligned.m16n8k16.row.col.f32.f16.f16.f32 "
    "{%0,%1,%2,%3}, {%4,%5,%6,%7}, {%8,%9}, {%0,%1,%2,%3};"
    : "+f"(d[0]), "+f"(d[1]), "+f"(d[2]), "+f"(d[3])
    : "r"(a[0]), "r"(a[1]), "r"(a[2]), "r"(a[3]), "r"(b[0]), "r"(b[1]));
}

// ---------------- W transpose + fp16 convert (R8-verified, ~5.6us) ----------------
__global__ void wt_kernel(const float* __restrict__ Wk, const float* __restrict__ Wq,
                          const float* __restrict__ Wv){
  const int n = blockIdx.x;
  const int c = n & 63;
  const float* W = (n < 64) ? Wq : (n < 128 ? Wk : Wv);
  for (int k = threadIdx.x; k < 384; k += 128)
    g_WTh[n*384 + k] = __float2half(W[k*64 + c]);
}

// ---------------- QKV projection: 512 threads, warp grid 4(M)x4(N), tile 32x48 ------
// Same smem layouts / ldmatrix mappings as R14 (verified); C shrinks to 48 floats so
// 16 warps fit -> 4 warps/SMSP, halving exposed sync/ldmatrix latency bubbles.
__global__ __launch_bounds__(512) void qkv_mma(const float* __restrict__ x){
  __shared__ __half Ash[128*40];   // [m][k] pitch 40 halves
  __shared__ __half Bsh[192*40];   // [n][k] pitch 40 halves
  const int tid = threadIdx.x, lane = tid & 31, warp = tid >> 5;
  const int g = lane >> 2, tig = lane & 3;
  const int wm = warp >> 2, wn = warp & 3;     // 4 x 4
  const int m0 = blockIdx.x * 128;

  float C[2][6][4];
  #pragma unroll
  for (int mf = 0; mf < 2; mf++)
    #pragma unroll
    for (int nf = 0; nf < 6; nf++)
      { C[mf][nf][0]=0.f; C[mf][nf][1]=0.f; C[mf][nf][2]=0.f; C[mf][nf][3]=0.f; }

  // ldmatrix per-lane address bases (layouts unchanged from R14)
  const int a_ro = lane & 15;
  const int a_co = (lane & 16) >> 1;
  const int b_ro = (lane & 7) | ((lane & 16) >> 1);
  const int b_co = lane & 8;
  const uint32_t a_base = smem_u32(Ash) + 2*((wm*32 + a_ro)*40 + a_co);
  const uint32_t b_base = smem_u32(Bsh) + 2*((wn*48 + b_ro)*40 + b_co);

  // prefetch: A = 1024 float4 (2 rounds of 512); B = 768 uint4 (1 round + half round)
  const int ar[2] = { tid>>3, (tid+512)>>3 };
  const int ac = tid & 7;
  const int bn0 = tid >> 2, bn1 = (tid + 512) >> 2;   // bn1 valid for tid<256
  const int bc = tid & 3;
  const uint4* Wg = (const uint4*)g_WTh;

  float4 ra[2]; uint4 rb0, rb1;
  ra[0] = *(const float4*)(x + (size_t)(m0 + ar[0])*384 + ac*4);
  ra[1] = *(const float4*)(x + (size_t)(m0 + ar[1])*384 + ac*4);
  rb0 = Wg[bn0*48 + bc];
  if (tid < 256) rb1 = Wg[bn1*48 + bc];

  #pragma unroll 1
  for (int ti = 0; ti < 12; ti++){
    // commit prefetched tile
    #pragma unroll
    for (int it = 0; it < 2; it++){
      uint2 h2 = make_uint2(pkh2(ra[it].x, ra[it].y), pkh2(ra[it].z, ra[it].w));
      *(uint2*)(Ash + ar[it]*40 + ac*4) = h2;
    }
    *(uint4*)(Bsh + bn0*40 + bc*8) = rb0;
    if (tid < 256) *(uint4*)(Bsh + bn1*40 + bc*8) = rb1;
    __syncthreads();

    if (ti < 11){   // prefetch next k-tile (flies during the MMAs)
      const int kn = (ti + 1) * 32;
      ra[0] = *(const float4*)(x + (size_t)(m0 + ar[0])*384 + kn + ac*4);
      ra[1] = *(const float4*)(x + (size_t)(m0 + ar[1])*384 + kn + ac*4);
      rb0 = Wg[bn0*48 + kn/8 + bc];
      if (tid < 256) rb1 = Wg[bn1*48 + kn/8 + bc];
    }

    #pragma unroll
    for (int ks = 0; ks < 2; ks++){
      uint32_t a[2][4];
      #pragma unroll
      for (int mf = 0; mf < 2; mf++)
        ldm_x4(a[mf], a_base + mf*1280 + ks*32);
      uint32_t bf[6][2];
      #pragma unroll
      for (int p = 0; p < 3; p++){
        uint32_t t[4];
        ldm_x4(t, b_base + p*1280 + ks*32);
        bf[2*p  ][0] = t[0]; bf[2*p  ][1] = t[1];
        bf[2*p+1][0] = t[2]; bf[2*p+1][1] = t[3];
      }
      #pragma unroll
      for (int nf = 0; nf < 6; nf++)
        #pragma unroll
        for (int mf = 0; mf < 2; mf++)
          mma16n8k16(C[mf][nf], a[mf], bf[nf]);
    }
    __syncthreads();
  }

  // Epilogue: q scaled by 0.125*log2(e); k [t][h]; v [b][h][t]
  const float QS = 0.18033688f;
  const int bb = m0 >> 8;
  #pragma unroll
  for (int mf = 0; mf < 2; mf++){
    const int mlo = m0 + wm*32 + mf*16 + g;
    const int t = mlo & 255;
    #pragma unroll
    for (int nf = 0; nf < 6; nf++){
      const int n = wn*48 + nf*8 + 2*tig;
      const int id = n >> 6, h = n & 63;
      if (id == 2){         // v
        __half* base = g_vTh + (size_t)bb*16384;
        base[(h  )*256 + t    ] = __float2half(C[mf][nf][0]);
        base[(h+1)*256 + t    ] = __float2half(C[mf][nf][1]);
        base[(h  )*256 + t + 8] = __float2half(C[mf][nf][2]);
        base[(h+1)*256 + t + 8] = __float2half(C[mf][nf][3]);
      } else if (id == 1){  // k
        *(uint32_t*)(g_kh + (size_t)(mlo  )*64 + h) = pkh2(C[mf][nf][0], C[mf][nf][1]);
        *(uint32_t*)(g_kh + (size_t)(mlo+8)*64 + h) = pkh2(C[mf][nf][2], C[mf][nf][3]);
      } else {              // q
        *(uint32_t*)(g_qh + (size_t)(mlo  )*64 + h) = pkh2(C[mf][nf][0]*QS, C[mf][nf][1]*QS);
        *(uint32_t*)(g_qh + (size_t)(mlo+8)*64 + h) = pkh2(C[mf][nf][2]*QS, C[mf][nf][3]*QS);
      }
    }
  }
}

// ---------------- fp16 flash attention (R12/R13-verified, 35.6us) ----------------
__global__ __launch_bounds__(512) void attn6(float* __restrict__ out){
  extern __shared__ __half smh[];
  __half* Ksh  = smh;            // [256][72]
  __half* Vtsh = smh + 256*72;   // [72][264]  rows 64..71: all ones
  const int b = blockIdx.x;
  const int tid = threadIdx.x, lane = tid & 31, w = tid >> 5;
  const int g = lane >> 2, tig = lane & 3;
  const uint32_t* Kw = (const uint32_t*)Ksh;
  const uint32_t* Vw = (const uint32_t*)Vtsh;

  {
    const uint4* Kg = (const uint4*)(g_kh  + (size_t)b*16384);
    const uint4* Vg = (const uint4*)(g_vTh + (size_t)b*16384);
    #pragma unroll
    for (int it = 0; it < 4; it++){
      int i = tid + 512*it;
      *(uint4*)(Ksh + (i>>3)*72 + (i&7)*8) = Kg[i];
      *(uint4*)(Vtsh + (i>>5)*264 + (i&31)*8) = Vg[i];
    }
    const __half one = __float2half(1.f);
    for (int i = tid; i < 2112; i += 512){
      int r = i/264, c1 = i - r*264;
      Vtsh[(64 + r)*264 + c1] = one;
    }
  }
  __syncthreads();

  const uint32_t* qp = (const uint32_t*)(g_qh + (size_t)b*16384);
  const int m0 = 16*w;

  uint32_t aq[4][4];
  #pragma unroll
  for (int ks = 0; ks < 4; ks++){
    const int ko = ks*8 + tig;
    aq[ks][0] = qp[(m0+g  )*32 + ko    ];
    aq[ks][1] = qp[(m0+g+8)*32 + ko    ];
    aq[ks][2] = qp[(m0+g  )*32 + ko + 4];
    aq[ks][3] = qp[(m0+g+8)*32 + ko + 4];
  }

  float O[9][4];
  #pragma unroll
  for (int jo = 0; jo < 9; jo++){ O[jo][0]=0.f; O[jo][1]=0.f; O[jo][2]=0.f; O[jo][3]=0.f; }
  const int cd = w >> 2;
  const int jmd = ((16*(w & 3) + 15) >> 3) + 1;   // 2,4,6,8 — live j-tiles on diagonal

  for (int c = 0; c <= cd; c++){
    const int jm = (c == cd) ? jmd : 8;
    float S[8][4];
    #pragma unroll
    for (int j = 0; j < 8; j++){ S[j][0]=0.f; S[j][1]=0.f; S[j][2]=0.f; S[j][3]=0.f; }

    #pragma unroll
    for (int ks = 0; ks < 4; ks++){
      const int ko = ks*8 + tig;
      #pragma unroll
      for (int j = 0; j < 8; j++){
        if (j < jm){
          const int kr = (c*64 + j*8 + g)*36 + ko;
          uint32_t bf[2] = { Kw[kr], Kw[kr + 4] };
          mma16n8k16(S[j], aq[ks], bf);
        }
      }
    }
    if (c == cd){   // causal mask: exp2(-100) == 0
      #pragma unroll
      for (int j = 0; j < 8; j++){
        if (j < jm){
          const int col = c*64 + j*8 + 2*tig;
          if (col     > m0+g  ) S[j][0] = -100.f;
          if (col + 1 > m0+g  ) S[j][1] = -100.f;
          if (col     > m0+g+8) S[j][2] = -100.f;
          if (col + 1 > m0+g+8) S[j][3] = -100.f;
        }
      }
    }

    #pragma unroll
    for (int kk = 0; kk < 4; kk++){
      if (2*kk < jm){
        uint32_t ap[4];
        ap[0] = hex2(pkh2(S[2*kk  ][0], S[2*kk  ][1]));
        ap[1] = hex2(pkh2(S[2*kk  ][2], S[2*kk  ][3]));
        ap[2] = hex2(pkh2(S[2*kk+1][0], S[2*kk+1][1]));
        ap[3] = hex2(pkh2(S[2*kk+1][2], S[2*kk+1][3]));
        const int tb = c*32 + kk*8 + tig;
        #pragma unroll
        for (int jo = 0; jo < 9; jo++){
          const int vr = (jo*8 + g)*132 + tb;
          uint32_t bv[2] = { Vw[vr], Vw[vr + 4] };
          mma16n8k16(O[jo], ap, bv);
        }
      }
    }
  }

  const float inv0 = 1.0f / O[8][0], inv1 = 1.0f / O[8][2];
  float* ob = out + (size_t)b*16384;
  #pragma unroll
  for (int jo = 0; jo < 8; jo++){
    *(float2*)(ob + (m0+g  )*64 + jo*8 + 2*tig) = make_float2(O[jo][0]*inv0, O[jo][1]*inv0);
    *(float2*)(ob + (m0+g+8)*64 + jo*8 + 2*tig) = make_float2(O[jo][2]*inv1, O[jo][3]*inv1);
  }
}

extern "C" void kernel_launch(void* const* d_in, const int* in_sizes, int n_in,
                              void* d_out, int out_size) {
  const float* x  = (const float*)d_in[0];
  const float* Wk = (const float*)d_in[1];
  const float* Wq = (const float*)d_in[2];
  const float* Wv = (const float*)d_in[3];
  float* out = (float*)d_out;
  (void)in_sizes; (void)n_in; (void)out_size;

  cudaFuncSetAttribute(attn6, cudaFuncAttributeMaxDynamicSharedMemorySize, 74880);

  wt_kernel<<<192, 128>>>(Wk, Wq, Wv);
  qkv_mma<<<1024, 512>>>(x);
  attn6<<<512, 512, 74880>>>(out);
}